// round 15
// baseline (speedup 1.0000x reference)
#include <cuda_runtime.h>
#include <cstdint>

#define N_NODES 100000
#define N_EDGES 1600000
#define H 128
#define AS_STRIDE 132

// Scratch: device globals (no allocation allowed). 16B-aligned.
__device__ __align__(16) float g_agg[(size_t)N_NODES * H];
__device__ __align__(16) float g_h1[(size_t)N_NODES * H];
__device__ __align__(16) int2  g_rec[(size_t)N_EDGES];     // {src, ew bits} sorted by dst
__device__ unsigned g_cnt[N_NODES + 1];
__device__ unsigned g_off[N_NODES + 1];
__device__ unsigned g_cur[N_NODES];
__device__ unsigned g_ctr1;
__device__ unsigned g_ctr2;

// ---------------------------------------------------------------------------
// CSR build 1: histogram of dst
// ---------------------------------------------------------------------------
__global__ void hist_kernel(const int* __restrict__ edge_index) {
    int e = blockIdx.x * blockDim.x + threadIdx.x;
    for (; e < N_EDGES; e += gridDim.x * blockDim.x) {
        int dst = edge_index[(long long)N_EDGES + e];
        atomicAdd(&g_cnt[dst], 1u);
    }
}

// ---------------------------------------------------------------------------
// CSR build 2: exclusive scan of counts (single block, 1024 threads).
// Also resets the GEMM tile counters.
// ---------------------------------------------------------------------------
__global__ void scan_kernel() {
    __shared__ unsigned s[1024];
    int ti = threadIdx.x;
    if (ti == 0) { g_ctr1 = 0; g_ctr2 = 0; }
    const int CH = (N_NODES + 1023) / 1024;   // 98
    int lo = ti * CH;
    int hi = min(lo + CH, N_NODES);
    unsigned sum = 0;
    for (int n = lo; n < hi; n++) sum += g_cnt[n];
    s[ti] = sum;
    __syncthreads();
    // Hillis-Steele inclusive scan
    for (int d = 1; d < 1024; d <<= 1) {
        unsigned v = (ti >= d) ? s[ti - d] : 0u;
        __syncthreads();
        s[ti] += v;
        __syncthreads();
    }
    unsigned running = s[ti] - sum;           // exclusive base for this chunk
    for (int n = lo; n < hi; n++) {
        g_off[n] = running;
        g_cur[n] = running;
        running += g_cnt[n];
    }
    if (ti == 1023) g_off[N_NODES] = s[1023];
}

// ---------------------------------------------------------------------------
// CSR build 3: permute edges into dst-grouped records {src, ew}
// ---------------------------------------------------------------------------
__global__ void permute_kernel(const int* __restrict__ edge_index,
                               const float* __restrict__ ew) {
    int e = blockIdx.x * blockDim.x + threadIdx.x;
    for (; e < N_EDGES; e += gridDim.x * blockDim.x) {
        int src = edge_index[e];
        int dst = edge_index[(long long)N_EDGES + e];
        float w = ew[e];
        unsigned pos = atomicAdd(&g_cur[dst], 1u);
        g_rec[pos] = make_int2(src, __float_as_int(w));
    }
}

// ---------------------------------------------------------------------------
// Aggregate: one warp per node.
//   agg[n] = x[n] + sum_e x[src_e] + (sum_e ew_e)*w_edge + deg*b_edge
// Unroll-4 edge loop for MLP=4 row gathers. Plain STG.128, no atomics.
// ---------------------------------------------------------------------------
__global__ void aggregate_kernel(const float* __restrict__ x,
                                 const float* __restrict__ w_edge,
                                 const float* __restrict__ b_edge) {
    int warp = blockIdx.x * (blockDim.x >> 5) + (threadIdx.x >> 5);
    int lane = threadIdx.x & 31;
    if (warp >= N_NODES) return;

    int start = (int)g_off[warp];
    int end = (int)g_off[warp + 1];

    float4 acc = ((const float4*)(x + (size_t)warp * H))[lane];  // self term
    float sw = 0.0f;

    int e = start;
    for (; e + 4 <= end; e += 4) {
        int2 r0 = g_rec[e];
        int2 r1 = g_rec[e + 1];
        int2 r2 = g_rec[e + 2];
        int2 r3 = g_rec[e + 3];
        float4 v0 = ((const float4*)(x + (size_t)r0.x * H))[lane];
        float4 v1 = ((const float4*)(x + (size_t)r1.x * H))[lane];
        float4 v2 = ((const float4*)(x + (size_t)r2.x * H))[lane];
        float4 v3 = ((const float4*)(x + (size_t)r3.x * H))[lane];
        sw += __int_as_float(r0.y) + __int_as_float(r1.y)
            + __int_as_float(r2.y) + __int_as_float(r3.y);
        acc.x += v0.x + v1.x + v2.x + v3.x;
        acc.y += v0.y + v1.y + v2.y + v3.y;
        acc.z += v0.z + v1.z + v2.z + v3.z;
        acc.w += v0.w + v1.w + v2.w + v3.w;
    }
    for (; e < end; e++) {
        int2 r = g_rec[e];
        float4 v = ((const float4*)(x + (size_t)r.x * H))[lane];
        sw += __int_as_float(r.y);
        acc.x += v.x; acc.y += v.y; acc.z += v.z; acc.w += v.w;
    }

    float4 wv = ((const float4*)w_edge)[lane];
    float4 bv = ((const float4*)b_edge)[lane];
    float deg = (float)(end - start);
    acc.x += sw * wv.x + deg * bv.x;
    acc.y += sw * wv.y + deg * bv.y;
    acc.z += sw * wv.z + deg * bv.z;
    acc.w += sw * wv.w + deg * bv.w;

    ((float4*)(g_agg + (size_t)warp * H))[lane] = acc;
}

// ---------------------------------------------------------------------------
// mma.sync tf32 GEMM (round-12 proven version): C = act(A @ W^T + bias).
// Persistent CTAs + dynamic tile counter, 128x128x128 tiles, 512 threads,
// warp grid 4m x 4n. A double-buffered via cp.async (raw fp32, cvt.rna on
// fragment load); W converted to tf32 once per CTA. Stride-132 smem.
// ---------------------------------------------------------------------------
#define MMA_TF32(d, a, b0, b1)                                                 \
    asm volatile("mma.sync.aligned.m16n8k8.row.col.f32.tf32.tf32.f32 "         \
                 "{%0,%1,%2,%3}, {%4,%5,%6,%7}, {%8,%9}, {%0,%1,%2,%3};"       \
                 : "+f"((d)[0]), "+f"((d)[1]), "+f"((d)[2]), "+f"((d)[3])      \
                 : "r"((a)[0]), "r"((a)[1]), "r"((a)[2]), "r"((a)[3]),         \
                   "r"(b0), "r"(b1))

__device__ __forceinline__ uint32_t cvt_tf32(float f) {
    uint32_t v;
    asm("cvt.rna.tf32.f32 %0, %1;" : "=r"(v) : "f"(f));
    return v;
}

__device__ __forceinline__ void load_As_async(float* Asb, const float* __restrict__ A,
                                              unsigned t, int nrows, int tid) {
    #pragma unroll
    for (int i = tid; i < 4096; i += 512) {
        int r = i >> 5;
        int c = (i & 31) * 4;
        int gr = (int)t * 128 + r;
        float* dgen = Asb + r * AS_STRIDE + c;
        uint32_t daddr = (uint32_t)__cvta_generic_to_shared(dgen);
        if (gr < nrows) {
            const float* src = A + (size_t)gr * 128 + c;
            asm volatile("cp.async.cg.shared.global [%0], [%1], 16;"
                         :: "r"(daddr), "l"(src));
        } else {
            *(float4*)dgen = make_float4(0.f, 0.f, 0.f, 0.f);
        }
    }
}

template <bool RELU>
__global__ __launch_bounds__(512, 1)
void gemm_mma_kernel(const float* __restrict__ A, const float* __restrict__ W,
                     const float* __restrict__ bias, float* __restrict__ C,
                     int nrows, unsigned* __restrict__ ctr) {
    extern __shared__ float sm[];
    float* Ws  = sm;                        // [128][132]: W[n][k] as tf32 bits
    float* As0 = sm + 128 * AS_STRIDE;
    float* As1 = As0 + 128 * AS_STRIDE;
    __shared__ float s_bias[128];
    __shared__ unsigned s_tile;

    int tid = threadIdx.x;
    int lane = tid & 31;
    int wid = tid >> 5;
    int wm = wid & 3;
    int wn = wid >> 2;
    int ntiles = (nrows + 127) >> 7;

    if (tid < 128) s_bias[tid] = bias[tid];

    #pragma unroll
    for (int i = tid; i < 4096; i += 512) {
        int r = i >> 5;
        int c = (i & 31) * 4;
        float4 w = *(const float4*)(W + r * 128 + c);
        uint4 u;
        u.x = cvt_tf32(w.x);
        u.y = cvt_tf32(w.y);
        u.z = cvt_tf32(w.z);
        u.w = cvt_tf32(w.w);
        *(uint4*)(Ws + r * AS_STRIDE + c) = u;
    }

    if (tid == 0) s_tile = atomicAdd(ctr, 1u);
    __syncthreads();
    unsigned t = s_tile;
    if (t >= (unsigned)ntiles) return;

    load_As_async(As0, A, t, nrows, tid);
    asm volatile("cp.async.commit_group;");
    int buf = 0;

    int qrow = lane >> 2;
    int qcol = lane & 3;

    while (true) {
        if (tid == 0) s_tile = atomicAdd(ctr, 1u);
        __syncthreads();
        unsigned tn = s_tile;
        bool have_next = (tn < (unsigned)ntiles);
        if (have_next) {
            load_As_async(buf ? As0 : As1, A, tn, nrows, tid);
            asm volatile("cp.async.commit_group;");
            asm volatile("cp.async.wait_group 1;");
        } else {
            asm volatile("cp.async.wait_group 0;");
        }
        __syncthreads();

        const float* Asb = buf ? As1 : As0;
        float acc[2][4][4];
        #pragma unroll
        for (int mt = 0; mt < 2; mt++)
            #pragma unroll
            for (int nt = 0; nt < 4; nt++)
                #pragma unroll
                for (int q = 0; q < 4; q++) acc[mt][nt][q] = 0.0f;

        #pragma unroll 4
        for (int ks = 0; ks < 16; ks++) {
            int k0 = ks * 8;
            uint32_t afrag[2][4];
            #pragma unroll
            for (int mt = 0; mt < 2; mt++) {
                int r0 = wm * 32 + mt * 16 + qrow;
                afrag[mt][0] = cvt_tf32(Asb[r0 * AS_STRIDE + k0 + qcol]);
                afrag[mt][1] = cvt_tf32(Asb[(r0 + 8) * AS_STRIDE + k0 + qcol]);
                afrag[mt][2] = cvt_tf32(Asb[r0 * AS_STRIDE + k0 + qcol + 4]);
                afrag[mt][3] = cvt_tf32(Asb[(r0 + 8) * AS_STRIDE + k0 + qcol + 4]);
            }
            #pragma unroll
            for (int nt = 0; nt < 4; nt++) {
                int n = wn * 32 + nt * 8 + qrow;
                uint32_t b0 = __float_as_uint(Ws[n * AS_STRIDE + k0 + qcol]);
                uint32_t b1 = __float_as_uint(Ws[n * AS_STRIDE + k0 + qcol + 4]);
                MMA_TF32(acc[0][nt], afrag[0], b0, b1);
                MMA_TF32(acc[1][nt], afrag[1], b0, b1);
            }
        }

        #pragma unroll
        for (int mt = 0; mt < 2; mt++) {
            int grow = (int)t * 128 + wm * 32 + mt * 16 + qrow;
            #pragma unroll
            for (int nt = 0; nt < 4; nt++) {
                int col = wn * 32 + nt * 8 + 2 * qcol;
                float2 o0, o1;
                o0.x = acc[mt][nt][0] + s_bias[col];
                o0.y = acc[mt][nt][1] + s_bias[col + 1];
                o1.x = acc[mt][nt][2] + s_bias[col];
                o1.y = acc[mt][nt][3] + s_bias[col + 1];
                if (RELU) {
                    o0.x = fmaxf(o0.x, 0.0f); o0.y = fmaxf(o0.y, 0.0f);
                    o1.x = fmaxf(o1.x, 0.0f); o1.y = fmaxf(o1.y, 0.0f);
                }
                if (grow < nrows)
                    *(float2*)&C[(size_t)grow * 128 + col] = o0;
                if (grow + 8 < nrows)
                    *(float2*)&C[(size_t)(grow + 8) * 128 + col] = o1;
            }
        }

        if (!have_next) break;
        t = tn;
        buf ^= 1;
    }
}

// ---------------------------------------------------------------------------
extern "C" void kernel_launch(void* const* d_in, const int* in_sizes, int n_in,
                              void* d_out, int out_size) {
    const float* x      = (const float*)d_in[0];
    const int*   ei     = (const int*)d_in[1];
    const float* ew     = (const float*)d_in[2];
    const float* w_edge = (const float*)d_in[3];
    const float* b_edge = (const float*)d_in[4];
    const float* w1     = (const float*)d_in[5];
    const float* b1     = (const float*)d_in[6];
    const float* w2     = (const float*)d_in[7];
    const float* b2     = (const float*)d_in[8];
    float*       out    = (float*)d_out;

    const int smem_bytes = 3 * 128 * AS_STRIDE * sizeof(float);  // 202752
    cudaFuncSetAttribute(gemm_mma_kernel<true>,
                         cudaFuncAttributeMaxDynamicSharedMemorySize, smem_bytes);
    cudaFuncSetAttribute(gemm_mma_kernel<false>,
                         cudaFuncAttributeMaxDynamicSharedMemorySize, smem_bytes);

    float* agg;
    float* h1;
    unsigned* cnt;
    unsigned* ctr1;
    unsigned* ctr2;
    cudaGetSymbolAddress((void**)&agg, g_agg);
    cudaGetSymbolAddress((void**)&h1, g_h1);
    cudaGetSymbolAddress((void**)&cnt, g_cnt);
    cudaGetSymbolAddress((void**)&ctr1, g_ctr1);
    cudaGetSymbolAddress((void**)&ctr2, g_ctr2);

    // CSR build: zero counts -> histogram -> scan -> permute
    cudaMemsetAsync(cnt, 0, (N_NODES + 1) * sizeof(unsigned), 0);
    hist_kernel<<<2048, 256>>>(ei);
    scan_kernel<<<1, 1024>>>();
    permute_kernel<<<2048, 256>>>(ei, ew);

    // Aggregate: one warp per node (folds in the self term; no init kernel)
    aggregate_kernel<<<(N_NODES + 7) / 8, 256>>>(x, w_edge, b_edge);

    // h1 = relu(agg @ w1^T + b1)
    gemm_mma_kernel<true><<<152, 512, smem_bytes>>>(agg, w1, b1, h1, N_NODES, ctr1);

    // out = h1 @ w2^T + b2
    gemm_mma_kernel<false><<<152, 512, smem_bytes>>>(h1, w2, b2, out, N_NODES, ctr2);
}